// round 2
// baseline (speedup 1.0000x reference)
#include <cuda_runtime.h>
#include <math.h>

#define NND 50000
#define NE  600000
#define AD  75
#define HH  128
#define NL  4
#define NG  128

// ---------------- scratch (static device globals; no runtime alloc) ----------------
__device__ float g_x  [NND*HH];
__device__ float g_h  [NND*HH];
__device__ float g_m  [NND*HH];
__device__ float g_agg[NND*HH];
__device__ float g_gi [NND*3*HH];
__device__ float g_gh [NND*3*HH];
__device__ float g_as [NND];
__device__ float g_ad [NND];
__device__ float g_stats[2*HH];
__device__ float g_gr [NG*HH];
__device__ float g_Wpad[HH*HH];

__device__ __forceinline__ float sigm(float v) { return 1.f / (1.f + expf(-v)); }

// ---------------- utility kernels ----------------
__global__ void k_zero(float* __restrict__ p, int n) {
    int i = blockIdx.x * blockDim.x + threadIdx.x;
    if (i < n) p[i] = 0.f;
}

__global__ void k_pad_nf(const float* __restrict__ nf, float* __restrict__ out) {
    int i = blockIdx.x * blockDim.x + threadIdx.x;
    if (i >= NND * HH) return;
    int n = i >> 7, c = i & 127;
    out[i] = (c < AD) ? nf[n * AD + c] : 0.f;
}

__global__ void k_pad_W(const float* __restrict__ w, float* __restrict__ out) {
    int i = blockIdx.x * blockDim.x + threadIdx.x;
    if (i >= HH * HH) return;
    int r = i >> 7, c = i & 127;
    out[i] = (c < AD) ? w[r * AD + c] : 0.f;
}

// ---------------- fp32 GEMM: C[M,D] = A[M,128] @ W[D,128]^T + bias ----------------
// 64x64 tile, 256 threads, 4x4 microtile, K chunked by 64, XOR-swizzled smem.
template <bool RELU>
__global__ __launch_bounds__(256) void k_gemm(
    const float* __restrict__ A, const float* __restrict__ W,
    const float* __restrict__ bias, float* __restrict__ C, int M, int D)
{
    __shared__ float As[64 * 64];
    __shared__ float Bs[64 * 64];
    int tid = threadIdx.x;
    int m0 = blockIdx.x * 64;
    int n0 = blockIdx.y * 64;
    int tm = tid & 15, tn = tid >> 4;
    float acc[4][4] = {};

    for (int kc = 0; kc < 2; kc++) {
        #pragma unroll
        for (int i = 0; i < 4; i++) {
            int flat = tid + i * 256;      // float4 index, 0..1023
            int row  = flat >> 4;          // 0..63
            int kq   = flat & 15;          // float4 within row (k/4)
            int col4 = row >> 2, rin = row & 3;
            int sc   = ((col4 ^ kq) << 2);
            float4 va = make_float4(0.f, 0.f, 0.f, 0.f);
            if (m0 + row < M)
                va = *(const float4*)(A + (size_t)(m0 + row) * 128 + kc * 64 + kq * 4);
            float4 vb = *(const float4*)(W + (size_t)(n0 + row) * 128 + kc * 64 + kq * 4);
            const float* pa = &va.x;
            const float* pb = &vb.x;
            #pragma unroll
            for (int j = 0; j < 4; j++) {
                int k = kq * 4 + j;
                As[k * 64 + sc + rin] = pa[j];
                Bs[k * 64 + sc + rin] = pb[j];
            }
        }
        __syncthreads();
        #pragma unroll 8
        for (int kk = 0; kk < 64; kk++) {
            int sw = kk >> 2;   // 0..15
            float4 a4 = *(const float4*)&As[kk * 64 + ((tm ^ sw) << 2)];
            float4 b4 = *(const float4*)&Bs[kk * 64 + ((tn ^ sw) << 2)];
            float av[4] = {a4.x, a4.y, a4.z, a4.w};
            float bv[4] = {b4.x, b4.y, b4.z, b4.w};
            #pragma unroll
            for (int i = 0; i < 4; i++)
                #pragma unroll
                for (int j = 0; j < 4; j++)
                    acc[i][j] += av[i] * bv[j];
        }
        __syncthreads();
    }

    float4 bb = *(const float4*)(bias + n0 + tn * 4);
    float bvv[4] = {bb.x, bb.y, bb.z, bb.w};
    #pragma unroll
    for (int i = 0; i < 4; i++) {
        int r = m0 + tm * 4 + i;
        if (r < M) {
            float4 o;
            float* po = &o.x;
            #pragma unroll
            for (int j = 0; j < 4; j++) {
                float v = acc[i][j] + bvv[j];
                if (RELU) v = fmaxf(v, 0.f);
                po[j] = v;
            }
            *(float4*)(C + (size_t)r * D + n0 + tn * 4) = o;
        }
    }
}

// ---------------- per-node attention projections: a_s = x . w1, a_d = x . w2 ----------------
__global__ void k_attdot(const float* __restrict__ x, const float* __restrict__ attW,
                         float* __restrict__ as_, float* __restrict__ ad_)
{
    int w = (blockIdx.x * blockDim.x + threadIdx.x) >> 5;
    int lane = threadIdx.x & 31;
    if (w >= NND) return;
    float4 xv = *(const float4*)(x + (size_t)w * HH + lane * 4);
    float4 w1 = *(const float4*)(attW + lane * 4);
    float4 w2 = *(const float4*)(attW + HH + lane * 4);
    float p1 = xv.x * w1.x + xv.y * w1.y + xv.z * w1.z + xv.w * w1.w;
    float p2 = xv.x * w2.x + xv.y * w2.y + xv.z * w2.z + xv.w * w2.w;
    #pragma unroll
    for (int o = 16; o > 0; o >>= 1) {
        p1 += __shfl_xor_sync(0xFFFFFFFFu, p1, o);
        p2 += __shfl_xor_sync(0xFFFFFFFFu, p2, o);
    }
    if (lane == 0) { as_[w] = p1; ad_[w] = p2; }
}

// ---------------- edge scatter: agg[dst] += m[src] * sigmoid(a_s[src]+a_d[dst]+b) ----------------
__global__ void k_edge(const int* __restrict__ ei, const float* __restrict__ m,
                       const float* __restrict__ as_, const float* __restrict__ ad_,
                       const float* __restrict__ attb, float* __restrict__ agg)
{
    int e = (blockIdx.x * blockDim.x + threadIdx.x) >> 5;
    int lane = threadIdx.x & 31;
    if (e >= NE) return;
    int s = __ldg(ei + e);
    int d = __ldg(ei + NE + e);
    float a = __ldg(as_ + s) + __ldg(ad_ + d) + __ldg(attb);
    float att = 1.f / (1.f + expf(-a));
    float4 v = *(const float4*)(m + (size_t)s * HH + lane * 4);
    float* p = agg + (size_t)d * HH + lane * 4;
    asm volatile("red.global.add.v4.f32 [%0], {%1, %2, %3, %4};"
                 :: "l"(p), "f"(v.x * att), "f"(v.y * att), "f"(v.z * att), "f"(v.w * att)
                 : "memory");
}

// ---------------- GRU elementwise ----------------
__global__ void k_gru(const float* __restrict__ gi, const float* __restrict__ gh,
                      const float* __restrict__ x, float* __restrict__ h)
{
    int idx = blockIdx.x * blockDim.x + threadIdx.x;
    if (idx >= NND * HH) return;
    int n = idx >> 7, c = idx & 127;
    const float* gin = gi + (size_t)n * 384;
    const float* ghn = gh + (size_t)n * 384;
    float r  = sigm(gin[c]       + ghn[c]);
    float z  = sigm(gin[c + 128] + ghn[c + 128]);
    float nn = tanhf(gin[c + 256] + r * ghn[c + 256]);
    h[idx] = (1.f - z) * nn + z * x[idx];
}

// ---------------- BatchNorm stats + normalize ----------------
__global__ void k_bnstats(const float* __restrict__ h, float* __restrict__ stats)
{
    __shared__ float ss[8][128];
    __shared__ float sq[8][128];
    int c = threadIdx.x;
    float s = 0.f, q = 0.f;
    for (int r = blockIdx.x * 8 + threadIdx.y; r < NND; r += gridDim.x * 8) {
        float v = h[(size_t)r * 128 + c];
        s += v; q += v * v;
    }
    ss[threadIdx.y][c] = s;
    sq[threadIdx.y][c] = q;
    __syncthreads();
    if (threadIdx.y == 0) {
        #pragma unroll
        for (int y = 1; y < 8; y++) { s += ss[y][c]; q += sq[y][c]; }
        atomicAdd(stats + c, s);
        atomicAdd(stats + 128 + c, q);
    }
}

__global__ void k_bnnorm(const float* __restrict__ h, const float* __restrict__ stats,
                         const float* __restrict__ g, const float* __restrict__ b,
                         float* __restrict__ x)
{
    int idx = blockIdx.x * blockDim.x + threadIdx.x;
    if (idx >= NND * HH) return;
    int c = idx & 127;
    float mu  = stats[c] * (1.f / NND);
    float var = stats[128 + c] * (1.f / NND) - mu * mu;
    x[idx] = (h[idx] - mu) * rsqrtf(var + 1e-5f) * g[c] + b[c];
}

// ---------------- graph sum-pool ----------------
__global__ void k_pool(const float* __restrict__ x, const int* __restrict__ bidx,
                       float* __restrict__ gr)
{
    int t = blockIdx.x * blockDim.x + threadIdx.x;
    if (t >= NND * 32) return;
    int n = t >> 5, q = t & 31;
    int g = __ldg(bidx + n);
    float4 v = *(const float4*)(x + (size_t)n * HH + q * 4);
    float* p = gr + (size_t)g * HH + q * 4;
    asm volatile("red.global.add.v4.f32 [%0], {%1, %2, %3, %4};"
                 :: "l"(p), "f"(v.x), "f"(v.y), "f"(v.z), "f"(v.w)
                 : "memory");
}

// ---------------- readout MLP ----------------
__global__ void k_readout(const float* __restrict__ gr, const float* __restrict__ W1,
                          const float* __restrict__ b1, const float* __restrict__ W2,
                          const float* __restrict__ b2, float* __restrict__ out)
{
    __shared__ float sred[64];
    int g = blockIdx.x, j = threadIdx.x;
    const float* grow = gr + (size_t)g * HH;
    const float* wrow = W1 + (size_t)j * HH;
    float acc = b1[j];
    #pragma unroll 8
    for (int k = 0; k < HH; k++) acc += grow[k] * wrow[k];
    acc = fmaxf(acc, 0.f) * W2[j];
    sred[j] = acc;
    __syncthreads();
    #pragma unroll
    for (int s = 32; s > 0; s >>= 1) {
        if (j < s) sred[j] += sred[j + s];
        __syncthreads();
    }
    if (j == 0) out[g] = sred[0] + b2[0];
}

// ---------------- host ----------------
static float* symaddr(const void* s) {
    void* p = nullptr;
    cudaGetSymbolAddress(&p, s);
    return (float*)p;
}

extern "C" void kernel_launch(void* const* d_in, const int* in_sizes, int n_in,
                              void* d_out, int out_size)
{
    const float* nf      = (const float*)d_in[0];
    const int*   ei      = (const int*)  d_in[1];
    const int*   bidx    = (const int*)  d_in[2];
    const float* emb_W   = (const float*)d_in[3];
    const float* emb_b   = (const float*)d_in[4];
    const float* emb_g   = (const float*)d_in[5];
    const float* emb_beta= (const float*)d_in[6];
    const float* msg_W   = (const float*)d_in[7];
    const float* msg_b   = (const float*)d_in[8];
    const float* att_W   = (const float*)d_in[9];
    const float* att_b   = (const float*)d_in[10];
    const float* gru_Wih = (const float*)d_in[11];
    const float* gru_bih = (const float*)d_in[12];
    const float* gru_Whh = (const float*)d_in[13];
    const float* gru_bhh = (const float*)d_in[14];
    const float* bn_g    = (const float*)d_in[15];
    const float* bn_b    = (const float*)d_in[16];
    const float* ro_W1   = (const float*)d_in[17];
    const float* ro_b1   = (const float*)d_in[18];
    const float* ro_W2   = (const float*)d_in[19];
    const float* ro_b2   = (const float*)d_in[20];
    float* out = (float*)d_out;

    float* x    = symaddr(g_x);
    float* h    = symaddr(g_h);
    float* m    = symaddr(g_m);
    float* agg  = symaddr(g_agg);
    float* gi   = symaddr(g_gi);
    float* gh   = symaddr(g_gh);
    float* as_  = symaddr(g_as);
    float* ad_  = symaddr(g_ad);
    float* st   = symaddr(g_stats);
    float* gr   = symaddr(g_gr);
    float* Wpad = symaddr(g_Wpad);

    const int NH = NND * HH;
    dim3 gemmB(256);
    dim3 grid128((NND + 63) / 64, 2);
    dim3 grid384((NND + 63) / 64, 6);
    dim3 bnB(128, 8);

    // ---- embedding: pad inputs to K=128, GEMM+ReLU, BN ----
    k_pad_W <<<(HH * HH + 255) / 256, 256>>>(emb_W, Wpad);
    k_pad_nf<<<(NH + 255) / 256, 256>>>(nf, agg);
    k_gemm<true><<<grid128, gemmB>>>(agg, Wpad, emb_b, h, NND, HH);
    k_zero<<<1, 256>>>(st, 2 * HH);
    k_bnstats<<<256, bnB>>>(h, st);
    k_bnnorm<<<(NH + 255) / 256, 256>>>(h, st, emb_g, emb_beta, x);

    // ---- 4 message-passing layers ----
    for (int l = 0; l < NL; l++) {
        k_gemm<false><<<grid128, gemmB>>>(x, msg_W + (size_t)l * HH * HH,
                                          msg_b + (size_t)l * HH, m, NND, HH);
        k_attdot<<<(NND * 32 + 255) / 256, 256>>>(x, att_W + (size_t)l * 2 * HH, as_, ad_);
        k_zero<<<(NH + 255) / 256, 256>>>(agg, NH);
        k_edge<<<(NE * 32 + 255) / 256, 256>>>(ei, m, as_, ad_, att_b + l, agg);
        k_gemm<false><<<grid384, gemmB>>>(agg, gru_Wih + (size_t)l * 3 * HH * HH,
                                          gru_bih + (size_t)l * 3 * HH, gi, NND, 3 * HH);
        k_gemm<false><<<grid384, gemmB>>>(x, gru_Whh + (size_t)l * 3 * HH * HH,
                                          gru_bhh + (size_t)l * 3 * HH, gh, NND, 3 * HH);
        k_gru<<<(NH + 255) / 256, 256>>>(gi, gh, x, h);
        k_zero<<<1, 256>>>(st, 2 * HH);
        k_bnstats<<<256, bnB>>>(h, st);
        k_bnnorm<<<(NH + 255) / 256, 256>>>(h, st, bn_g + (size_t)l * HH,
                                            bn_b + (size_t)l * HH, x);
    }

    // ---- readout ----
    k_zero<<<(NG * HH + 255) / 256, 256>>>(gr, NG * HH);
    k_pool<<<(NND * 32 + 255) / 256, 256>>>(x, bidx, gr);
    k_readout<<<NG, 64>>>(gr, ro_W1, ro_b1, ro_W2, ro_b2, out);

    (void)in_sizes; (void)n_in; (void)out_size;
}

// round 7
// speedup vs baseline: 1.3041x; 1.3041x over previous
#include <cuda_runtime.h>
#include <math.h>

#define NND 50000
#define NE  600000
#define AD  75
#define HH  128
#define NL  4
#define NG  128

// ---------------- scratch (static device globals; no runtime alloc) ----------------
__device__ float g_x  [NND*HH];
__device__ float g_h  [NND*HH];
__device__ float g_m  [NND*HH];
__device__ float g_agg[NND*HH];
__device__ float g_gi [NND*3*HH];
__device__ float g_gh [NND*3*HH];
__device__ float g_as [NND];
__device__ float g_ad [NND];
__device__ float g_stats[2*HH];
__device__ float g_gr [NG*HH];
__device__ float g_Wpad[HH*HH];

__device__ __forceinline__ float sigm(float v) { return 1.f / (1.f + expf(-v)); }

__device__ __forceinline__ unsigned f2tf(float x) {
    unsigned u;
    asm("cvt.rna.tf32.f32 %0, %1;" : "=r"(u) : "f"(x));
    return u;
}

// ---------------- utility kernels ----------------
__global__ void k_zero(float* __restrict__ p, int n) {
    int i = blockIdx.x * blockDim.x + threadIdx.x;
    if (i < n) p[i] = 0.f;
}

__global__ void k_pad_nf(const float* __restrict__ nf, float* __restrict__ out) {
    int i = blockIdx.x * blockDim.x + threadIdx.x;
    if (i >= NND * HH) return;
    int n = i >> 7, c = i & 127;
    out[i] = (c < AD) ? nf[n * AD + c] : 0.f;
}

__global__ void k_pad_W(const float* __restrict__ w, float* __restrict__ out) {
    int i = blockIdx.x * blockDim.x + threadIdx.x;
    if (i >= HH * HH) return;
    int r = i >> 7, c = i & 127;
    out[i] = (c < AD) ? w[r * AD + c] : 0.f;
}

// ---------------- tf32 tensor-core GEMM: C[M,D] = A[M,128] @ W[D,128]^T + bias ----------------
// 128x64 block tile, 256 threads = 8 warps (4 m x 2 n), each warp 32x32 via
// m16n8k8 mma.sync tiles (2 m-tiles x 4 n-tiles). Smem stride 36 -> conflict-free
// fragment loads. Inputs rounded to tf32 (rna) during staging.
template <bool RELU>
__global__ __launch_bounds__(256) void k_gemm_tc(
    const float* __restrict__ A, const float* __restrict__ W,
    const float* __restrict__ bias, float* __restrict__ C, int M, int D)
{
    __shared__ float As[128 * 36];
    __shared__ float Bs[64 * 36];
    const int tid = threadIdx.x;
    const int m0 = blockIdx.x * 128;
    const int n0 = blockIdx.y * 64;
    const int wid = tid >> 5;
    const int lane = tid & 31;
    const int wm = (wid & 3) * 32;   // warp m offset within tile
    const int wn = (wid >> 2) * 32;  // warp n offset within tile
    const int lr = lane >> 2;
    const int lc = lane & 3;

    float acc[2][4][4];
    #pragma unroll
    for (int i = 0; i < 2; i++)
        #pragma unroll
        for (int j = 0; j < 4; j++)
            #pragma unroll
            for (int q = 0; q < 4; q++) acc[i][j][q] = 0.f;

    for (int kc = 0; kc < 4; kc++) {           // K chunks of 32
        // stage A (128 x 32)
        #pragma unroll
        for (int i = 0; i < 4; i++) {
            int idx = tid + i * 256;           // float4 id, 0..1023
            int row = idx >> 3;
            int kq  = idx & 7;
            float4 v = make_float4(0.f, 0.f, 0.f, 0.f);
            int gr_ = m0 + row;
            if (gr_ < M)
                v = *(const float4*)(A + (size_t)gr_ * 128 + kc * 32 + kq * 4);
            float* d = &As[row * 36 + kq * 4];
            d[0] = __uint_as_float(f2tf(v.x));
            d[1] = __uint_as_float(f2tf(v.y));
            d[2] = __uint_as_float(f2tf(v.z));
            d[3] = __uint_as_float(f2tf(v.w));
        }
        // stage B (64 x 32)
        #pragma unroll
        for (int i = 0; i < 2; i++) {
            int idx = tid + i * 256;           // 0..511
            int row = idx >> 3;
            int kq  = idx & 7;
            float4 v = *(const float4*)(W + (size_t)(n0 + row) * 128 + kc * 32 + kq * 4);
            float* d = &Bs[row * 36 + kq * 4];
            d[0] = __uint_as_float(f2tf(v.x));
            d[1] = __uint_as_float(f2tf(v.y));
            d[2] = __uint_as_float(f2tf(v.z));
            d[3] = __uint_as_float(f2tf(v.w));
        }
        __syncthreads();

        #pragma unroll
        for (int k8 = 0; k8 < 4; k8++) {
            const int kb = k8 * 8;
            unsigned a[2][4];
            #pragma unroll
            for (int mt = 0; mt < 2; mt++) {
                const float* pa = &As[(wm + mt * 16 + lr) * 36 + kb + lc];
                a[mt][0] = __float_as_uint(pa[0]);
                a[mt][1] = __float_as_uint(pa[8 * 36]);
                a[mt][2] = __float_as_uint(pa[4]);
                a[mt][3] = __float_as_uint(pa[8 * 36 + 4]);
            }
            unsigned b[4][2];
            #pragma unroll
            for (int nt = 0; nt < 4; nt++) {
                const float* pb = &Bs[(wn + nt * 8 + lr) * 36 + kb + lc];
                b[nt][0] = __float_as_uint(pb[0]);
                b[nt][1] = __float_as_uint(pb[4]);
            }
            #pragma unroll
            for (int mt = 0; mt < 2; mt++)
                #pragma unroll
                for (int nt = 0; nt < 4; nt++) {
                    asm volatile(
                        "mma.sync.aligned.m16n8k8.row.col.f32.tf32.tf32.f32 "
                        "{%0,%1,%2,%3}, {%4,%5,%6,%7}, {%8,%9}, {%0,%1,%2,%3};\n"
                        : "+f"(acc[mt][nt][0]), "+f"(acc[mt][nt][1]),
                          "+f"(acc[mt][nt][2]), "+f"(acc[mt][nt][3])
                        : "r"(a[mt][0]), "r"(a[mt][1]), "r"(a[mt][2]), "r"(a[mt][3]),
                          "r"(b[nt][0]), "r"(b[nt][1]));
                }
        }
        __syncthreads();
    }

    // epilogue
    #pragma unroll
    for (int mt = 0; mt < 2; mt++) {
        #pragma unroll
        for (int nt = 0; nt < 4; nt++) {
            int cb = n0 + wn + nt * 8 + lc * 2;
            float2 bv = *(const float2*)(bias + cb);
            int r0 = m0 + wm + mt * 16 + lr;
            if (r0 < M) {
                float2 o;
                o.x = acc[mt][nt][0] + bv.x;
                o.y = acc[mt][nt][1] + bv.y;
                if (RELU) { o.x = fmaxf(o.x, 0.f); o.y = fmaxf(o.y, 0.f); }
                *(float2*)(C + (size_t)r0 * D + cb) = o;
            }
            int r1 = r0 + 8;
            if (r1 < M) {
                float2 o;
                o.x = acc[mt][nt][2] + bv.x;
                o.y = acc[mt][nt][3] + bv.y;
                if (RELU) { o.x = fmaxf(o.x, 0.f); o.y = fmaxf(o.y, 0.f); }
                *(float2*)(C + (size_t)r1 * D + cb) = o;
            }
        }
    }
}

// ---------------- edge scatter: agg[dst] += m[src] * sigmoid(a_s[src]+a_d[dst]+b) ----------------
__global__ void k_edge(const int* __restrict__ ei, const float* __restrict__ m,
                       const float* __restrict__ as_, const float* __restrict__ ad_,
                       const float* __restrict__ attb, float* __restrict__ agg)
{
    int e = (blockIdx.x * blockDim.x + threadIdx.x) >> 5;
    int lane = threadIdx.x & 31;
    if (e >= NE) return;
    int s = __ldg(ei + e);
    int d = __ldg(ei + NE + e);
    float a = __ldg(as_ + s) + __ldg(ad_ + d) + __ldg(attb);
    float att = 1.f / (1.f + expf(-a));
    float4 v = *(const float4*)(m + (size_t)s * HH + lane * 4);
    float* p = agg + (size_t)d * HH + lane * 4;
    asm volatile("red.global.add.v4.f32 [%0], {%1, %2, %3, %4};"
                 :: "l"(p), "f"(v.x * att), "f"(v.y * att), "f"(v.z * att), "f"(v.w * att)
                 : "memory");
}

// ---------------- fused GRU elementwise + BN stats ----------------
__global__ __launch_bounds__(256) void k_gru_bn(
    const float* __restrict__ gi, const float* __restrict__ gh,
    const float* __restrict__ x, float* __restrict__ h, float* __restrict__ stats)
{
    __shared__ float ss[256];
    __shared__ float sq[256];
    int c  = threadIdx.x & 127;
    int ry = threadIdx.x >> 7;
    float s = 0.f, q = 0.f;
    for (int r = blockIdx.x * 2 + ry; r < NND; r += gridDim.x * 2) {
        const float* gin = gi + (size_t)r * 384;
        const float* ghn = gh + (size_t)r * 384;
        float rr = sigm(gin[c]       + ghn[c]);
        float zz = sigm(gin[c + 128] + ghn[c + 128]);
        float nn = tanhf(gin[c + 256] + rr * ghn[c + 256]);
        float v  = (1.f - zz) * nn + zz * x[(size_t)r * 128 + c];
        h[(size_t)r * 128 + c] = v;
        s += v; q += v * v;
    }
    ss[threadIdx.x] = s;
    sq[threadIdx.x] = q;
    __syncthreads();
    if (threadIdx.x < 128) {
        atomicAdd(stats + c, ss[threadIdx.x] + ss[threadIdx.x + 128]);
        atomicAdd(stats + 128 + c, sq[threadIdx.x] + sq[threadIdx.x + 128]);
    }
}

// ---------------- BN stats (standalone, for embedding stage) ----------------
__global__ void k_bnstats(const float* __restrict__ h, float* __restrict__ stats)
{
    __shared__ float ss[8][128];
    __shared__ float sq[8][128];
    int c = threadIdx.x;
    float s = 0.f, q = 0.f;
    for (int r = blockIdx.x * 8 + threadIdx.y; r < NND; r += gridDim.x * 8) {
        float v = h[(size_t)r * 128 + c];
        s += v; q += v * v;
    }
    ss[threadIdx.y][c] = s;
    sq[threadIdx.y][c] = q;
    __syncthreads();
    if (threadIdx.y == 0) {
        #pragma unroll
        for (int y = 1; y < 8; y++) { s += ss[y][c]; q += sq[y][c]; }
        atomicAdd(stats + c, s);
        atomicAdd(stats + 128 + c, q);
    }
}

// ---------------- fused BN normalize + (next-layer attention dots | graph pool) ----------------
// One warp per node row. mode 0: write x + compute a_s/a_d with attW.
// mode 1: write x + scatter into graph sum-pool.
__global__ void k_bn_fuse(const float* __restrict__ h, const float* __restrict__ stats,
                          const float* __restrict__ g, const float* __restrict__ b,
                          const float* __restrict__ attW,
                          float* __restrict__ x, float* __restrict__ as_, float* __restrict__ ad_,
                          const int* __restrict__ bidx, float* __restrict__ gr, int mode)
{
    int w = (blockIdx.x * blockDim.x + threadIdx.x) >> 5;
    int lane = threadIdx.x & 31;
    if (w >= NND) return;
    float4 hv = *(const float4*)(h + (size_t)w * HH + lane * 4);
    float4 s1 = *(const float4*)(stats + lane * 4);
    float4 s2 = *(const float4*)(stats + 128 + lane * 4);
    float4 gg = *(const float4*)(g + lane * 4);
    float4 bb = *(const float4*)(b + lane * 4);
    const float inv = 1.f / NND;
    float4 v;
    {
        float mu = s1.x * inv, var = s2.x * inv - mu * mu;
        v.x = (hv.x - mu) * rsqrtf(var + 1e-5f) * gg.x + bb.x;
        mu = s1.y * inv; var = s2.y * inv - mu * mu;
        v.y = (hv.y - mu) * rsqrtf(var + 1e-5f) * gg.y + bb.y;
        mu = s1.z * inv; var = s2.z * inv - mu * mu;
        v.z = (hv.z - mu) * rsqrtf(var + 1e-5f) * gg.z + bb.z;
        mu = s1.w * inv; var = s2.w * inv - mu * mu;
        v.w = (hv.w - mu) * rsqrtf(var + 1e-5f) * gg.w + bb.w;
    }
    *(float4*)(x + (size_t)w * HH + lane * 4) = v;

    if (mode == 0) {
        float4 w1 = *(const float4*)(attW + lane * 4);
        float4 w2 = *(const float4*)(attW + HH + lane * 4);
        float p1 = v.x * w1.x + v.y * w1.y + v.z * w1.z + v.w * w1.w;
        float p2 = v.x * w2.x + v.y * w2.y + v.z * w2.z + v.w * w2.w;
        #pragma unroll
        for (int o = 16; o > 0; o >>= 1) {
            p1 += __shfl_xor_sync(0xFFFFFFFFu, p1, o);
            p2 += __shfl_xor_sync(0xFFFFFFFFu, p2, o);
        }
        if (lane == 0) { as_[w] = p1; ad_[w] = p2; }
    } else {
        int gidx = __ldg(bidx + w);
        float* p = gr + (size_t)gidx * HH + lane * 4;
        asm volatile("red.global.add.v4.f32 [%0], {%1, %2, %3, %4};"
                     :: "l"(p), "f"(v.x), "f"(v.y), "f"(v.z), "f"(v.w)
                     : "memory");
    }
}

// ---------------- readout MLP ----------------
__global__ void k_readout(const float* __restrict__ gr, const float* __restrict__ W1,
                          const float* __restrict__ b1, const float* __restrict__ W2,
                          const float* __restrict__ b2, float* __restrict__ out)
{
    __shared__ float sred[64];
    int g = blockIdx.x, j = threadIdx.x;
    const float* grow = gr + (size_t)g * HH;
    const float* wrow = W1 + (size_t)j * HH;
    float acc = b1[j];
    #pragma unroll 8
    for (int k = 0; k < HH; k++) acc += grow[k] * wrow[k];
    acc = fmaxf(acc, 0.f) * W2[j];
    sred[j] = acc;
    __syncthreads();
    #pragma unroll
    for (int s = 32; s > 0; s >>= 1) {
        if (j < s) sred[j] += sred[j + s];
        __syncthreads();
    }
    if (j == 0) out[g] = sred[0] + b2[0];
}

// ---------------- host ----------------
static float* symaddr(const void* s) {
    void* p = nullptr;
    cudaGetSymbolAddress(&p, s);
    return (float*)p;
}

extern "C" void kernel_launch(void* const* d_in, const int* in_sizes, int n_in,
                              void* d_out, int out_size)
{
    const float* nf      = (const float*)d_in[0];
    const int*   ei      = (const int*)  d_in[1];
    const int*   bidx    = (const int*)  d_in[2];
    const float* emb_W   = (const float*)d_in[3];
    const float* emb_b   = (const float*)d_in[4];
    const float* emb_g   = (const float*)d_in[5];
    const float* emb_beta= (const float*)d_in[6];
    const float* msg_W   = (const float*)d_in[7];
    const float* msg_b   = (const float*)d_in[8];
    const float* att_W   = (const float*)d_in[9];
    const float* att_b   = (const float*)d_in[10];
    const float* gru_Wih = (const float*)d_in[11];
    const float* gru_bih = (const float*)d_in[12];
    const float* gru_Whh = (const float*)d_in[13];
    const float* gru_bhh = (const float*)d_in[14];
    const float* bn_g    = (const float*)d_in[15];
    const float* bn_b    = (const float*)d_in[16];
    const float* ro_W1   = (const float*)d_in[17];
    const float* ro_b1   = (const float*)d_in[18];
    const float* ro_W2   = (const float*)d_in[19];
    const float* ro_b2   = (const float*)d_in[20];
    float* out = (float*)d_out;

    float* x    = symaddr(g_x);
    float* h    = symaddr(g_h);
    float* m    = symaddr(g_m);
    float* agg  = symaddr(g_agg);
    float* gi   = symaddr(g_gi);
    float* gh   = symaddr(g_gh);
    float* as_  = symaddr(g_as);
    float* ad_  = symaddr(g_ad);
    float* st   = symaddr(g_stats);
    float* gr   = symaddr(g_gr);
    float* Wpad = symaddr(g_Wpad);

    const int NH = NND * HH;
    dim3 gemmB(256);
    dim3 grid128((NND + 127) / 128, 2);
    dim3 grid384((NND + 127) / 128, 6);
    dim3 bnB(128, 8);

    // ---- embedding: pad inputs to K=128, tf32 GEMM+ReLU, BN (+layer0 att dots) ----
    k_pad_W <<<(HH * HH + 255) / 256, 256>>>(emb_W, Wpad);
    k_pad_nf<<<(NH + 255) / 256, 256>>>(nf, m);
    k_gemm_tc<true><<<grid128, gemmB>>>(m, Wpad, emb_b, h, NND, HH);
    k_zero<<<1, 256>>>(st, 2 * HH);
    k_bnstats<<<256, bnB>>>(h, st);
    k_bn_fuse<<<(NND * 32 + 255) / 256, 256>>>(h, st, emb_g, emb_beta, att_W,
                                               x, as_, ad_, bidx, gr, 0);

    // ---- 4 message-passing layers ----
    for (int l = 0; l < NL; l++) {
        k_gemm_tc<false><<<grid128, gemmB>>>(x, msg_W + (size_t)l * HH * HH,
                                             msg_b + (size_t)l * HH, m, NND, HH);
        k_zero<<<(NH + 255) / 256, 256>>>(agg, NH);
        k_edge<<<(NE * 32 + 255) / 256, 256>>>(ei, m, as_, ad_, att_b + l, agg);
        k_gemm_tc<false><<<grid384, gemmB>>>(agg, gru_Wih + (size_t)l * 3 * HH * HH,
                                             gru_bih + (size_t)l * 3 * HH, gi, NND, 3 * HH);
        k_gemm_tc<false><<<grid384, gemmB>>>(x, gru_Whh + (size_t)l * 3 * HH * HH,
                                             gru_bhh + (size_t)l * 3 * HH, gh, NND, 3 * HH);
        k_zero<<<1, 256>>>(st, 2 * HH);
        k_gru_bn<<<256, 256>>>(gi, gh, x, h, st);
        if (l < NL - 1) {
            k_bn_fuse<<<(NND * 32 + 255) / 256, 256>>>(
                h, st, bn_g + (size_t)l * HH, bn_b + (size_t)l * HH,
                att_W + (size_t)(l + 1) * 2 * HH, x, as_, ad_, bidx, gr, 0);
        } else {
            k_zero<<<(NG * HH + 255) / 256, 256>>>(gr, NG * HH);
            k_bn_fuse<<<(NND * 32 + 255) / 256, 256>>>(
                h, st, bn_g + (size_t)l * HH, bn_b + (size_t)l * HH,
                att_W, x, as_, ad_, bidx, gr, 1);
        }
    }

    // ---- readout ----
    k_readout<<<NG, 64>>>(gr, ro_W1, ro_b1, ro_W2, ro_b2, out);

    (void)in_sizes; (void)n_in; (void)out_size;
}

// round 8
// speedup vs baseline: 1.5145x; 1.1613x over previous
#include <cuda_runtime.h>
#include <math.h>

#define NND 50000
#define NE  600000
#define AD  75
#define HH  128
#define NL  4
#define NG  128
#define NB1 196   // ceil(NND/256)

// ---------------- scratch (static device globals; no runtime alloc) ----------------
__device__ float g_x  [NND*HH];
__device__ float g_h  [NND*HH];
__device__ float g_m  [NND*HH];
__device__ float g_agg[NND*HH];
__device__ float g_gi [NND*3*HH];
__device__ float g_gh [NND*3*HH];
__device__ float g_as [NND];
__device__ float g_ad [NND];
__device__ float g_stats[2*HH];
__device__ float g_gr [NG*HH];
__device__ float g_Wpad[HH*HH];
__device__ float g_Wmh [NL*512*HH];
__device__ float g_bmh [NL*512];
__device__ int   g_deg [NND];
__device__ int   g_off [NND+1];
__device__ int   g_cur [NND];
__device__ int   g_blk [256];
__device__ int   g_esrc[NE];
__device__ int   g_edst[NE];
__device__ float g_eatt[NE];

__device__ __forceinline__ float sigm(float v) { return 1.f / (1.f + expf(-v)); }

__device__ __forceinline__ unsigned f2tf(float x) {
    unsigned u;
    asm("cvt.rna.tf32.f32 %0, %1;" : "=r"(u) : "f"(x));
    return u;
}

// ---------------- setup: pads + weight packing ----------------
__global__ void k_prep(const float* __restrict__ nf, const float* __restrict__ embW,
                       const float* __restrict__ msgW, const float* __restrict__ msgb,
                       const float* __restrict__ Whh, const float* __restrict__ bhh,
                       float* __restrict__ nfp, float* __restrict__ Wpad,
                       float* __restrict__ Wmh, float* __restrict__ bmh)
{
    int i = blockIdx.x * blockDim.x + threadIdx.x;
    if (i < NND * HH) {
        int n = i >> 7, c = i & 127;
        nfp[i] = (c < AD) ? nf[n * AD + c] : 0.f;
    }
    if (i < HH * HH) {
        int r = i >> 7, c = i & 127;
        Wpad[i] = (c < AD) ? embW[r * AD + c] : 0.f;
    }
    if (i < NL * 512 * HH) {
        int l = i / (512 * HH);
        int rem = i - l * 512 * HH;
        int r = rem >> 7, c = rem & 127;
        Wmh[i] = (r < HH) ? msgW[(size_t)l * HH * HH + r * HH + c]
                          : Whh[(size_t)l * 3 * HH * HH + (size_t)(r - HH) * HH + c];
    }
    if (i < NL * 512) {
        int l = i >> 9, r = i & 511;
        bmh[i] = (r < HH) ? msgb[l * HH + r] : bhh[l * 3 * HH + (r - HH)];
    }
}

__global__ void k_zinit(int* __restrict__ deg, float* __restrict__ gr)
{
    int i = blockIdx.x * blockDim.x + threadIdx.x;
    if (i < NND) deg[i] = 0;
    if (i < NG * HH) gr[i] = 0.f;
}

// ---------------- CSR build ----------------
__global__ void k_hist(const int* __restrict__ ei, int* __restrict__ deg)
{
    int e = blockIdx.x * blockDim.x + threadIdx.x;
    if (e < NE) atomicAdd(deg + __ldg(ei + NE + e), 1);
}

__global__ void k_scan1(const int* __restrict__ deg, int* __restrict__ off,
                        int* __restrict__ blk)
{
    __shared__ int s[256];
    int tx = threadIdx.x;
    int i = blockIdx.x * 256 + tx;
    int v = (i < NND) ? deg[i] : 0;
    s[tx] = v;
    __syncthreads();
    for (int o = 1; o < 256; o <<= 1) {
        int t = 0;
        if (tx >= o) t = s[tx - o];
        __syncthreads();
        if (tx >= o) s[tx] += t;
        __syncthreads();
    }
    if (i < NND) off[i] = s[tx] - v;   // exclusive within block
    if (tx == 255) blk[blockIdx.x] = s[255];
}

__global__ void k_scan2(int* __restrict__ blk)
{
    __shared__ int s[256];
    int tx = threadIdx.x;
    int v = (tx < NB1) ? blk[tx] : 0;
    s[tx] = v;
    __syncthreads();
    for (int o = 1; o < 256; o <<= 1) {
        int t = 0;
        if (tx >= o) t = s[tx - o];
        __syncthreads();
        if (tx >= o) s[tx] += t;
        __syncthreads();
    }
    blk[tx] = s[tx] - v;               // exclusive block offsets
}

__global__ void k_scan3(int* __restrict__ off, const int* __restrict__ blk,
                        int* __restrict__ cur)
{
    int i = blockIdx.x * 256 + threadIdx.x;
    if (i < NND) {
        int o = off[i] + blk[i >> 8];
        off[i] = o;
        cur[i] = o;
    }
    if (i == 0) off[NND] = NE;
}

__global__ void k_fill(const int* __restrict__ ei, int* __restrict__ cur,
                       int* __restrict__ esrc, int* __restrict__ edst)
{
    int e = blockIdx.x * blockDim.x + threadIdx.x;
    if (e >= NE) return;
    int s = __ldg(ei + e);
    int d = __ldg(ei + NE + e);
    int pos = atomicAdd(cur + d, 1);
    esrc[pos] = s;
    edst[pos] = d;
}

// ---------------- per-edge attention (CSR order) ----------------
__global__ void k_att(const int* __restrict__ esrc, const int* __restrict__ edst,
                      const float* __restrict__ as_, const float* __restrict__ ad_,
                      const float* __restrict__ attb, float* __restrict__ eatt)
{
    int p = blockIdx.x * blockDim.x + threadIdx.x;
    if (p >= NE) return;
    float a = __ldg(as_ + __ldg(esrc + p)) + __ldg(ad_ + __ldg(edst + p)) + __ldg(attb);
    eatt[p] = 1.f / (1.f + expf(-a));
}

// ---------------- gather aggregation: agg[n] = sum_{e in CSR(n)} m[src[e]] * att[e] ----------------
__global__ __launch_bounds__(256) void k_gather(
    const int* __restrict__ off, const int* __restrict__ esrc,
    const float* __restrict__ eatt, const float* __restrict__ m,
    float* __restrict__ agg)
{
    int n = (blockIdx.x * blockDim.x + threadIdx.x) >> 5;
    int lane = threadIdx.x & 31;
    if (n >= NND) return;
    int p = __ldg(off + n);
    int e = __ldg(off + n + 1);
    float4 acc = make_float4(0.f, 0.f, 0.f, 0.f);
    for (; p + 1 < e; p += 2) {
        int s0 = __ldg(esrc + p);
        int s1 = __ldg(esrc + p + 1);
        float a0 = __ldg(eatt + p);
        float a1 = __ldg(eatt + p + 1);
        float4 v0 = *(const float4*)(m + (size_t)s0 * HH + lane * 4);
        float4 v1 = *(const float4*)(m + (size_t)s1 * HH + lane * 4);
        acc.x += v0.x * a0 + v1.x * a1;
        acc.y += v0.y * a0 + v1.y * a1;
        acc.z += v0.z * a0 + v1.z * a1;
        acc.w += v0.w * a0 + v1.w * a1;
    }
    if (p < e) {
        int s0 = __ldg(esrc + p);
        float a0 = __ldg(eatt + p);
        float4 v0 = *(const float4*)(m + (size_t)s0 * HH + lane * 4);
        acc.x += v0.x * a0; acc.y += v0.y * a0;
        acc.z += v0.z * a0; acc.w += v0.w * a0;
    }
    *(float4*)(agg + (size_t)n * HH + lane * 4) = acc;
}

// ---------------- tf32 tensor-core GEMM with split output + reg-prefetch pipeline ----------------
// C[:, c<split] -> C1 (stride s1), C[:, c>=split] -> C2 at col c-split (stride s2).
template <bool RELU>
__global__ __launch_bounds__(256) void k_gemm_tc(
    const float* __restrict__ A, const float* __restrict__ W,
    const float* __restrict__ bias, float* __restrict__ C1, float* __restrict__ C2,
    int M, int split, int s1, int s2, float* zbuf)
{
    __shared__ float As[128 * 36];
    __shared__ float Bs[64 * 36];
    const int tid = threadIdx.x;
    if (zbuf != nullptr && blockIdx.x == 0 && blockIdx.y == 0 && tid < 256)
        zbuf[tid] = 0.f;
    const int m0 = blockIdx.x * 128;
    const int n0 = blockIdx.y * 64;
    const int wid = tid >> 5;
    const int lane = tid & 31;
    const int wm = (wid & 3) * 32;
    const int wn = (wid >> 2) * 32;
    const int lr = lane >> 2;
    const int lc = lane & 3;

    float* Cp; int cstr, coff;
    if (n0 < split) { Cp = C1; cstr = s1; coff = 0; }
    else            { Cp = C2; cstr = s2; coff = split; }

    int arow[4], akq[4];
    #pragma unroll
    for (int i = 0; i < 4; i++) {
        int idx = tid + i * 256;
        arow[i] = idx >> 3;
        akq[i]  = idx & 7;
    }
    // brow = arow[0..1], bkq = akq[0..1] reuse

    float acc[2][4][4];
    #pragma unroll
    for (int i = 0; i < 2; i++)
        #pragma unroll
        for (int j = 0; j < 4; j++)
            #pragma unroll
            for (int q = 0; q < 4; q++) acc[i][j][q] = 0.f;

    float4 pa[4], pb[2];
    // prefetch chunk 0
    #pragma unroll
    for (int i = 0; i < 4; i++) {
        pa[i] = make_float4(0.f, 0.f, 0.f, 0.f);
        if (m0 + arow[i] < M)
            pa[i] = *(const float4*)(A + (size_t)(m0 + arow[i]) * 128 + akq[i] * 4);
    }
    #pragma unroll
    for (int i = 0; i < 2; i++)
        pb[i] = *(const float4*)(W + (size_t)(n0 + arow[i]) * 128 + akq[i] * 4);

    for (int kc = 0; kc < 4; kc++) {
        // store current regs to smem (with tf32 rounding)
        #pragma unroll
        for (int i = 0; i < 4; i++) {
            float* d = &As[arow[i] * 36 + akq[i] * 4];
            d[0] = __uint_as_float(f2tf(pa[i].x));
            d[1] = __uint_as_float(f2tf(pa[i].y));
            d[2] = __uint_as_float(f2tf(pa[i].z));
            d[3] = __uint_as_float(f2tf(pa[i].w));
        }
        #pragma unroll
        for (int i = 0; i < 2; i++) {
            float* d = &Bs[arow[i] * 36 + akq[i] * 4];
            d[0] = __uint_as_float(f2tf(pb[i].x));
            d[1] = __uint_as_float(f2tf(pb[i].y));
            d[2] = __uint_as_float(f2tf(pb[i].z));
            d[3] = __uint_as_float(f2tf(pb[i].w));
        }
        __syncthreads();
        // prefetch next chunk while MMAs run
        if (kc < 3) {
            int kb = (kc + 1) * 32;
            #pragma unroll
            for (int i = 0; i < 4; i++) {
                pa[i] = make_float4(0.f, 0.f, 0.f, 0.f);
                if (m0 + arow[i] < M)
                    pa[i] = *(const float4*)(A + (size_t)(m0 + arow[i]) * 128 + kb + akq[i] * 4);
            }
            #pragma unroll
            for (int i = 0; i < 2; i++)
                pb[i] = *(const float4*)(W + (size_t)(n0 + arow[i]) * 128 + kb + akq[i] * 4);
        }

        #pragma unroll
        for (int k8 = 0; k8 < 4; k8++) {
            const int kb = k8 * 8;
            unsigned a[2][4];
            #pragma unroll
            for (int mt = 0; mt < 2; mt++) {
                const float* p = &As[(wm + mt * 16 + lr) * 36 + kb + lc];
                a[mt][0] = __float_as_uint(p[0]);
                a[mt][1] = __float_as_uint(p[8 * 36]);
                a[mt][2] = __float_as_uint(p[4]);
                a[mt][3] = __float_as_uint(p[8 * 36 + 4]);
            }
            unsigned b[4][2];
            #pragma unroll
            for (int nt = 0; nt < 4; nt++) {
                const float* p = &Bs[(wn + nt * 8 + lr) * 36 + kb + lc];
                b[nt][0] = __float_as_uint(p[0]);
                b[nt][1] = __float_as_uint(p[4]);
            }
            #pragma unroll
            for (int mt = 0; mt < 2; mt++)
                #pragma unroll
                for (int nt = 0; nt < 4; nt++) {
                    asm volatile(
                        "mma.sync.aligned.m16n8k8.row.col.f32.tf32.tf32.f32 "
                        "{%0,%1,%2,%3}, {%4,%5,%6,%7}, {%8,%9}, {%0,%1,%2,%3};\n"
                        : "+f"(acc[mt][nt][0]), "+f"(acc[mt][nt][1]),
                          "+f"(acc[mt][nt][2]), "+f"(acc[mt][nt][3])
                        : "r"(a[mt][0]), "r"(a[mt][1]), "r"(a[mt][2]), "r"(a[mt][3]),
                          "r"(b[nt][0]), "r"(b[nt][1]));
                }
        }
        __syncthreads();
    }

    #pragma unroll
    for (int mt = 0; mt < 2; mt++) {
        #pragma unroll
        for (int nt = 0; nt < 4; nt++) {
            int cb = n0 + wn + nt * 8 + lc * 2;
            float2 bv = *(const float2*)(bias + cb);
            int cc = cb - coff;
            int r0 = m0 + wm + mt * 16 + lr;
            if (r0 < M) {
                float2 o;
                o.x = acc[mt][nt][0] + bv.x;
                o.y = acc[mt][nt][1] + bv.y;
                if (RELU) { o.x = fmaxf(o.x, 0.f); o.y = fmaxf(o.y, 0.f); }
                *(float2*)(Cp + (size_t)r0 * cstr + cc) = o;
            }
            int r1 = r0 + 8;
            if (r1 < M) {
                float2 o;
                o.x = acc[mt][nt][2] + bv.x;
                o.y = acc[mt][nt][3] + bv.y;
                if (RELU) { o.x = fmaxf(o.x, 0.f); o.y = fmaxf(o.y, 0.f); }
                *(float2*)(Cp + (size_t)r1 * cstr + cc) = o;
            }
        }
    }
}

// ---------------- fused GRU elementwise + BN stats ----------------
__global__ __launch_bounds__(256) void k_gru_bn(
    const float* __restrict__ gi, const float* __restrict__ gh,
    const float* __restrict__ x, float* __restrict__ h, float* __restrict__ stats)
{
    __shared__ float ss[256];
    __shared__ float sq[256];
    int c  = threadIdx.x & 127;
    int ry = threadIdx.x >> 7;
    float s = 0.f, q = 0.f;
    for (int r = blockIdx.x * 2 + ry; r < NND; r += gridDim.x * 2) {
        const float* gin = gi + (size_t)r * 384;
        const float* ghn = gh + (size_t)r * 384;
        float rr = sigm(gin[c]       + ghn[c]);
        float zz = sigm(gin[c + 128] + ghn[c + 128]);
        float nn = tanhf(gin[c + 256] + rr * ghn[c + 256]);
        float v  = (1.f - zz) * nn + zz * x[(size_t)r * 128 + c];
        h[(size_t)r * 128 + c] = v;
        s += v; q += v * v;
    }
    ss[threadIdx.x] = s;
    sq[threadIdx.x] = q;
    __syncthreads();
    if (threadIdx.x < 128) {
        atomicAdd(stats + c, ss[threadIdx.x] + ss[threadIdx.x + 128]);
        atomicAdd(stats + 128 + c, sq[threadIdx.x] + sq[threadIdx.x + 128]);
    }
}

// ---------------- BN stats (embedding stage) ----------------
__global__ void k_bnstats(const float* __restrict__ h, float* __restrict__ stats)
{
    __shared__ float ss[8][128];
    __shared__ float sq[8][128];
    int c = threadIdx.x;
    float s = 0.f, q = 0.f;
    for (int r = blockIdx.x * 8 + threadIdx.y; r < NND; r += gridDim.x * 8) {
        float v = h[(size_t)r * 128 + c];
        s += v; q += v * v;
    }
    ss[threadIdx.y][c] = s;
    sq[threadIdx.y][c] = q;
    __syncthreads();
    if (threadIdx.y == 0) {
        #pragma unroll
        for (int y = 1; y < 8; y++) { s += ss[y][c]; q += sq[y][c]; }
        atomicAdd(stats + c, s);
        atomicAdd(stats + 128 + c, q);
    }
}

// ---------------- fused BN normalize + (attention dots | graph pool) ----------------
__global__ void k_bn_fuse(const float* __restrict__ h, const float* __restrict__ stats,
                          const float* __restrict__ g, const float* __restrict__ b,
                          const float* __restrict__ attW,
                          float* __restrict__ x, float* __restrict__ as_, float* __restrict__ ad_,
                          const int* __restrict__ bidx, float* __restrict__ gr, int mode)
{
    int w = (blockIdx.x * blockDim.x + threadIdx.x) >> 5;
    int lane = threadIdx.x & 31;
    if (w >= NND) return;
    float4 hv = *(const float4*)(h + (size_t)w * HH + lane * 4);
    float4 s1 = *(const float4*)(stats + lane * 4);
    float4 s2 = *(const float4*)(stats + 128 + lane * 4);
    float4 gg = *(const float4*)(g + lane * 4);
    float4 bb = *(const float4*)(b + lane * 4);
    const float inv = 1.f / NND;
    float4 v;
    {
        float mu = s1.x * inv, var = s2.x * inv - mu * mu;
        v.x = (hv.x - mu) * rsqrtf(var + 1e-5f) * gg.x + bb.x;
        mu = s1.y * inv; var = s2.y * inv - mu * mu;
        v.y = (hv.y - mu) * rsqrtf(var + 1e-5f) * gg.y + bb.y;
        mu = s1.z * inv; var = s2.z * inv - mu * mu;
        v.z = (hv.z - mu) * rsqrtf(var + 1e-5f) * gg.z + bb.z;
        mu = s1.w * inv; var = s2.w * inv - mu * mu;
        v.w = (hv.w - mu) * rsqrtf(var + 1e-5f) * gg.w + bb.w;
    }
    *(float4*)(x + (size_t)w * HH + lane * 4) = v;

    if (mode == 0) {
        float4 w1 = *(const float4*)(attW + lane * 4);
        float4 w2 = *(const float4*)(attW + HH + lane * 4);
        float p1 = v.x * w1.x + v.y * w1.y + v.z * w1.z + v.w * w1.w;
        float p2 = v.x * w2.x + v.y * w2.y + v.z * w2.z + v.w * w2.w;
        #pragma unroll
        for (int o = 16; o > 0; o >>= 1) {
            p1 += __shfl_xor_sync(0xFFFFFFFFu, p1, o);
            p2 += __shfl_xor_sync(0xFFFFFFFFu, p2, o);
        }
        if (lane == 0) { as_[w] = p1; ad_[w] = p2; }
    } else {
        int gidx = __ldg(bidx + w);
        float* p = gr + (size_t)gidx * HH + lane * 4;
        asm volatile("red.global.add.v4.f32 [%0], {%1, %2, %3, %4};"
                     :: "l"(p), "f"(v.x), "f"(v.y), "f"(v.z), "f"(v.w)
                     : "memory");
    }
}

// ---------------- readout MLP ----------------
__global__ void k_readout(const float* __restrict__ gr, const float* __restrict__ W1,
                          const float* __restrict__ b1, const float* __restrict__ W2,
                          const float* __restrict__ b2, float* __restrict__ out)
{
    __shared__ float sred[64];
    int g = blockIdx.x, j = threadIdx.x;
    const float* grow = gr + (size_t)g * HH;
    const float* wrow = W1 + (size_t)j * HH;
    float acc = b1[j];
    #pragma unroll 8
    for (int k = 0; k < HH; k++) acc += grow[k] * wrow[k];
    acc = fmaxf(acc, 0.f) * W2[j];
    sred[j] = acc;
    __syncthreads();
    #pragma unroll
    for (int s = 32; s > 0; s >>= 1) {
        if (j < s) sred[j] += sred[j + s];
        __syncthreads();
    }
    if (j == 0) out[g] = sred[0] + b2[0];
}

// ---------------- host ----------------
static float* symaddrf(const void* s) { void* p = nullptr; cudaGetSymbolAddress(&p, s); return (float*)p; }
static int*   symaddri(const void* s) { void* p = nullptr; cudaGetSymbolAddress(&p, s); return (int*)p; }

extern "C" void kernel_launch(void* const* d_in, const int* in_sizes, int n_in,
                              void* d_out, int out_size)
{
    const float* nf      = (const float*)d_in[0];
    const int*   ei      = (const int*)  d_in[1];
    const int*   bidx    = (const int*)  d_in[2];
    const float* emb_W   = (const float*)d_in[3];
    const float* emb_b   = (const float*)d_in[4];
    const float* emb_g   = (const float*)d_in[5];
    const float* emb_beta= (const float*)d_in[6];
    const float* msg_W   = (const float*)d_in[7];
    const float* msg_b   = (const float*)d_in[8];
    const float* att_W   = (const float*)d_in[9];
    const float* att_b   = (const float*)d_in[10];
    const float* gru_Wih = (const float*)d_in[11];
    const float* gru_bih = (const float*)d_in[12];
    const float* gru_Whh = (const float*)d_in[13];
    const float* gru_bhh = (const float*)d_in[14];
    const float* bn_g    = (const float*)d_in[15];
    const float* bn_b    = (const float*)d_in[16];
    const float* ro_W1   = (const float*)d_in[17];
    const float* ro_b1   = (const float*)d_in[18];
    const float* ro_W2   = (const float*)d_in[19];
    const float* ro_b2   = (const float*)d_in[20];
    float* out = (float*)d_out;

    float* x    = symaddrf(g_x);
    float* h    = symaddrf(g_h);
    float* m    = symaddrf(g_m);
    float* agg  = symaddrf(g_agg);
    float* gi   = symaddrf(g_gi);
    float* gh   = symaddrf(g_gh);
    float* as_  = symaddrf(g_as);
    float* ad_  = symaddrf(g_ad);
    float* st   = symaddrf(g_stats);
    float* gr   = symaddrf(g_gr);
    float* Wpad = symaddrf(g_Wpad);
    float* Wmh  = symaddrf(g_Wmh);
    float* bmh  = symaddrf(g_bmh);
    float* eatt = symaddrf(g_eatt);
    int* deg  = symaddri(g_deg);
    int* off  = symaddri(g_off);
    int* cur  = symaddri(g_cur);
    int* blk  = symaddri(g_blk);
    int* esrc = symaddri(g_esrc);
    int* edst = symaddri(g_edst);

    const int NH = NND * HH;
    dim3 gemmB(256);
    dim3 gridMB((NND + 127) / 128, 2);   // emb GEMM (D=128)
    dim3 gridMH((NND + 127) / 128, 8);   // fused m+gh GEMM (D=512)
    dim3 gridGI((NND + 127) / 128, 6);   // gi GEMM (D=384)
    dim3 bnB(128, 8);

    // ---- setup: pads, weight packing, CSR build ----
    k_prep<<<(NH + 255) / 256, 256>>>(nf, emb_W, msg_W, msg_b, gru_Whh, gru_bhh,
                                      m, Wpad, Wmh, bmh);
    k_zinit<<<(NND + 255) / 256, 256>>>(deg, gr);
    k_hist<<<(NE + 255) / 256, 256>>>(ei, deg);
    k_scan1<<<NB1, 256>>>(deg, off, blk);
    k_scan2<<<1, 256>>>(blk);
    k_scan3<<<NB1, 256>>>(off, blk, cur);
    k_fill<<<(NE + 255) / 256, 256>>>(ei, cur, esrc, edst);

    // ---- embedding: tf32 GEMM+ReLU (zeroes stats), BN stats, BN+layer0 att dots ----
    k_gemm_tc<true><<<gridMB, gemmB>>>(m, Wpad, emb_b, h, h, NND, 128, 128, 128, st);
    k_bnstats<<<256, bnB>>>(h, st);
    k_bn_fuse<<<(NND * 32 + 255) / 256, 256>>>(h, st, emb_g, emb_beta, att_W,
                                               x, as_, ad_, bidx, gr, 0);

    // ---- 4 message-passing layers ----
    for (int l = 0; l < NL; l++) {
        k_att<<<(NE + 255) / 256, 256>>>(esrc, edst, as_, ad_, att_b + l, eatt);
        k_gemm_tc<false><<<gridMH, gemmB>>>(x, Wmh + (size_t)l * 512 * HH,
                                            bmh + (size_t)l * 512,
                                            m, gh, NND, 128, 128, 384, nullptr);
        k_gather<<<(NND * 32 + 255) / 256, 256>>>(off, esrc, eatt, m, agg);
        k_gemm_tc<false><<<gridGI, gemmB>>>(agg, gru_Wih + (size_t)l * 3 * HH * HH,
                                            gru_bih + (size_t)l * 3 * HH,
                                            gi, gi, NND, 384, 384, 384, st);
        k_gru_bn<<<256, 256>>>(gi, gh, x, h, st);
        if (l < NL - 1) {
            k_bn_fuse<<<(NND * 32 + 255) / 256, 256>>>(
                h, st, bn_g + (size_t)l * HH, bn_b + (size_t)l * HH,
                att_W + (size_t)(l + 1) * 2 * HH, x, as_, ad_, bidx, gr, 0);
        } else {
            k_bn_fuse<<<(NND * 32 + 255) / 256, 256>>>(
                h, st, bn_g + (size_t)l * HH, bn_b + (size_t)l * HH,
                att_W, x, as_, ad_, bidx, gr, 1);
        }
    }

    // ---- readout ----
    k_readout<<<NG, 64>>>(gr, ro_W1, ro_b1, ro_W2, ro_b2, out);

    (void)in_sizes; (void)n_in; (void)out_size;
}